// round 1
// baseline (speedup 1.0000x reference)
#include <cuda_runtime.h>
#include <cuda_bf16.h>
#include <math.h>

#define Bsz 512
#define Ssz 512
#define Tsz 128
#define NEGV -10000.0f

// scratch (no allocations allowed)
__device__ float g_fwd[Bsz];
__device__ float g_gold[Bsz];

// ---------------------------------------------------------------------------
// Forward scan: one CTA per batch, 256 threads.
// Thread (i = tid&127, h = tid>>7) holds E[i][h*64 .. h*64+63] in registers,
// where E = exp(transition). Per step:
//   m = max_j alpha[j]; p[j] = exp(alpha[j]-m);
//   s[i] = sum_j E[i][j]*p[j];  alpha[i] = m + log(s[i]) + x[b,t,i]
// Early-break when mask hits 0 (mask is monotone non-increasing per batch).
// ---------------------------------------------------------------------------
__global__ __launch_bounds__(256, 2)
void crf_forward_kernel(const float* __restrict__ x,
                        const float* __restrict__ mask,
                        const float* __restrict__ trans)
{
    __shared__ float sh_alpha[Tsz];
    __shared__ float sh_p[Tsz];
    __shared__ float sh_s1[Tsz];
    __shared__ float sh_red[4];
    __shared__ float sh_sum[4];

    const int b    = blockIdx.x;
    const int tid  = threadIdx.x;
    const int i    = tid & 127;
    const int h    = tid >> 7;       // 0 or 1
    const int warp = tid >> 5;       // 0..7
    const int lane = tid & 31;

    // Load E row segment into registers: e[jj] = exp(trans[i][h*64+jj])
    float e[64];
    const float4* trow = reinterpret_cast<const float4*>(trans + i * Tsz + h * 64);
    #pragma unroll
    for (int q = 0; q < 16; q++) {
        float4 v4 = trow[q];
        e[q*4 + 0] = __expf(v4.x);
        e[q*4 + 1] = __expf(v4.y);
        e[q*4 + 2] = __expf(v4.z);
        e[q*4 + 3] = __expf(v4.w);
    }

    if (h == 0) sh_alpha[i] = (i == 0) ? 0.0f : NEGV;   // START_ID = 0
    __syncthreads();

    const float* xb = x + (size_t)b * Ssz * Tsz;
    const float* mb = mask + (size_t)b * Ssz;

    for (int t = 0; t < Ssz; t++) {
        float mt = mb[t];                 // same address for all threads (broadcast)
        if (mt == 0.0f) break;            // mask is monotone -> all later steps frozen

        // ---- max reduce over alpha (both halves compute, h==0 writes) ----
        float v = sh_alpha[i];
        float wm = v;
        #pragma unroll
        for (int off = 16; off > 0; off >>= 1)
            wm = fmaxf(wm, __shfl_xor_sync(0xffffffffu, wm, off));
        if (h == 0 && lane == 0) sh_red[warp] = wm;
        __syncthreads();

        float m = fmaxf(fmaxf(sh_red[0], sh_red[1]), fmaxf(sh_red[2], sh_red[3]));
        if (h == 0) sh_p[i] = __expf(v - m);
        __syncthreads();

        // ---- matvec partial: s = sum over this thread's 64 j's ----
        const float* ph = sh_p + h * 64;
        float a0 = 0.f, a1 = 0.f, a2 = 0.f, a3 = 0.f;
        #pragma unroll
        for (int jj = 0; jj < 64; jj += 4) {
            a0 = fmaf(e[jj + 0], ph[jj + 0], a0);
            a1 = fmaf(e[jj + 1], ph[jj + 1], a1);
            a2 = fmaf(e[jj + 2], ph[jj + 2], a2);
            a3 = fmaf(e[jj + 3], ph[jj + 3], a3);
        }
        float s = (a0 + a1) + (a2 + a3);
        if (h == 1) sh_s1[i] = s;
        __syncthreads();

        if (h == 0) {
            float tot = s + sh_s1[i];
            sh_alpha[i] = m + __logf(tot) + xb[(size_t)t * Tsz + i];
        }
        __syncthreads();
    }

    // ---- final: fwd[b] = LSE_i(alpha[i] + trans[END_ID=1][i]) ----
    float v = sh_alpha[i] + trans[1 * Tsz + i];
    float wm = v;
    #pragma unroll
    for (int off = 16; off > 0; off >>= 1)
        wm = fmaxf(wm, __shfl_xor_sync(0xffffffffu, wm, off));
    if (h == 0 && lane == 0) sh_red[warp] = wm;
    __syncthreads();
    float m = fmaxf(fmaxf(sh_red[0], sh_red[1]), fmaxf(sh_red[2], sh_red[3]));

    float ev = __expf(v - m);
    float ws = ev;
    #pragma unroll
    for (int off = 16; off > 0; off >>= 1)
        ws += __shfl_xor_sync(0xffffffffu, ws, off);
    __syncthreads();                       // sh_red reads done before sh_sum writes race-free
    if (h == 0 && lane == 0) sh_sum[warp] = ws;
    __syncthreads();
    if (tid == 0)
        g_fwd[b] = m + __logf(sh_sum[0] + sh_sum[1] + sh_sum[2] + sh_sum[3]);
}

// ---------------------------------------------------------------------------
// Gold score: one CTA (128 threads) per batch.
// score = sum_{t<S-1} (x[b,t,tags[b,t+1]] + trans[tags[b,t+1]][tags[b,t]]) * mask[b,t]
//         + trans[END_ID][tags[b, len]]   where len = sum(mask[b,:])
// ---------------------------------------------------------------------------
__global__ __launch_bounds__(128)
void crf_gold_kernel(const float* __restrict__ x,
                     const int*   __restrict__ tags,
                     const float* __restrict__ mask,
                     const float* __restrict__ trans)
{
    __shared__ float sh_acc[4];
    __shared__ int   sh_len[4];

    const int b    = blockIdx.x;
    const int tid  = threadIdx.x;
    const int warp = tid >> 5;
    const int lane = tid & 31;

    const int*   tg = tags + (size_t)b * Ssz;
    const float* mk = mask + (size_t)b * Ssz;

    float acc = 0.0f;
    int   len = 0;
    for (int t = tid; t < Ssz - 1; t += 128) {
        float mt = mk[t];
        if (mt != 0.0f) {
            int tnext = tg[t + 1];
            int tcur  = tg[t];
            float em  = x[((size_t)b * Ssz + t) * Tsz + tnext];
            float tr  = trans[tnext * Tsz + tcur];
            acc += em + tr;      // mt == 1.0 exactly
            len += 1;
        }
    }
    #pragma unroll
    for (int off = 16; off > 0; off >>= 1) {
        acc += __shfl_xor_sync(0xffffffffu, acc, off);
        len += __shfl_xor_sync(0xffffffffu, len, off);
    }
    if (lane == 0) { sh_acc[warp] = acc; sh_len[warp] = len; }
    __syncthreads();
    if (tid == 0) {
        float total = sh_acc[0] + sh_acc[1] + sh_acc[2] + sh_acc[3];
        int   L     = sh_len[0] + sh_len[1] + sh_len[2] + sh_len[3];
        int last_tag = tg[L];
        g_gold[b] = total + trans[1 * Tsz + last_tag];   // END_ID = 1
    }
}

// ---------------------------------------------------------------------------
// Final: out[0] = mean(fwd - gold)
// ---------------------------------------------------------------------------
__global__ __launch_bounds__(512)
void crf_reduce_kernel(float* __restrict__ out)
{
    __shared__ float sh[16];
    const int tid  = threadIdx.x;
    const int warp = tid >> 5;
    const int lane = tid & 31;

    float d = g_fwd[tid] - g_gold[tid];
    #pragma unroll
    for (int off = 16; off > 0; off >>= 1)
        d += __shfl_xor_sync(0xffffffffu, d, off);
    if (lane == 0) sh[warp] = d;
    __syncthreads();
    if (warp == 0) {
        float v = (lane < 16) ? sh[lane] : 0.0f;
        #pragma unroll
        for (int off = 8; off > 0; off >>= 1)
            v += __shfl_xor_sync(0xffffffffu, v, off);
        if (lane == 0) out[0] = v * (1.0f / (float)Bsz);
    }
}

extern "C" void kernel_launch(void* const* d_in, const int* in_sizes, int n_in,
                              void* d_out, int out_size)
{
    const float* x     = (const float*)d_in[0];
    const int*   tags  = (const int*)  d_in[1];
    const float* mask  = (const float*)d_in[2];
    const float* trans = (const float*)d_in[3];
    float* out = (float*)d_out;

    crf_forward_kernel<<<Bsz, 256>>>(x, mask, trans);
    crf_gold_kernel  <<<Bsz, 128>>>(x, tags, mask, trans);
    crf_reduce_kernel<<<1, 512>>>(out);
}

// round 2
// speedup vs baseline: 2.4406x; 2.4406x over previous
#include <cuda_runtime.h>
#include <cuda_bf16.h>
#include <math.h>

#define Bsz 512
#define Ssz 512
#define Tsz 128
#define NEGV -10000.0f

// scratch (no allocations allowed)
__device__ float g_fwd[Bsz];
__device__ float g_gold[Bsz];
__device__ int   g_len[Bsz];
__device__ int   g_order[Bsz];
__device__ int   g_slen[Bsz];

// ---- packed f32x2 helpers (sm_100+) ----
__device__ __forceinline__ unsigned long long pack2(float lo, float hi) {
    unsigned long long r;
    asm("mov.b64 %0, {%1, %2};" : "=l"(r) : "f"(lo), "f"(hi));
    return r;
}
__device__ __forceinline__ void ffma2(unsigned long long& d,
                                      unsigned long long a,
                                      unsigned long long b) {
    asm("fma.rn.f32x2 %0, %1, %2, %0;" : "+l"(d) : "l"(a), "l"(b));
}
__device__ __forceinline__ unsigned long long addp(unsigned long long a,
                                                   unsigned long long b) {
    unsigned long long r;
    asm("add.rn.f32x2 %0, %1, %2;" : "=l"(r) : "l"(a), "l"(b));
    return r;
}
__device__ __forceinline__ float unpack_sum(unsigned long long a) {
    float lo, hi;
    asm("mov.b64 {%0, %1}, %2;" : "=f"(lo), "=f"(hi) : "l"(a));
    return lo + hi;
}

// ---------------------------------------------------------------------------
// Kernel 1: lengths.  len[b] = sum(mask[b,:])
// ---------------------------------------------------------------------------
__global__ __launch_bounds__(128)
void crf_len_kernel(const float* __restrict__ mask)
{
    __shared__ float sh[4];
    const int b = blockIdx.x, tid = threadIdx.x;
    const int warp = tid >> 5, lane = tid & 31;
    float s = 0.f;
    const float* mb = mask + (size_t)b * Ssz;
    #pragma unroll
    for (int t = tid; t < Ssz; t += 128) s += mb[t];
    #pragma unroll
    for (int off = 16; off > 0; off >>= 1)
        s += __shfl_xor_sync(0xffffffffu, s, off);
    if (lane == 0) sh[warp] = s;
    __syncthreads();
    if (tid == 0)
        g_len[b] = (int)(sh[0] + sh[1] + sh[2] + sh[3] + 0.5f);
}

// ---------------------------------------------------------------------------
// Kernel 2: bitonic sort 512 (len,b) keys, descending by len (longest first).
// key = (len<<16)|b  -> unique, deterministic.
// ---------------------------------------------------------------------------
__global__ __launch_bounds__(512)
void crf_sort_kernel()
{
    __shared__ int keys[Bsz];
    const int tid = threadIdx.x;
    keys[tid] = (g_len[tid] << 16) | tid;
    __syncthreads();
    for (int k = 2; k <= Bsz; k <<= 1) {
        for (int j = k >> 1; j > 0; j >>= 1) {
            int ixj = tid ^ j;
            if (ixj > tid) {
                int a = keys[tid];
                int b2 = keys[ixj];
                bool up = ((tid & k) == 0);   // descending overall
                if (up ? (a < b2) : (a > b2)) {
                    keys[tid] = b2;
                    keys[ixj] = a;
                }
            }
            __syncthreads();
        }
    }
    g_order[tid] = keys[tid] & 0xFFFF;
    g_slen[tid]  = keys[tid] >> 16;
}

// ---------------------------------------------------------------------------
// Kernel 3: forward scan. One CTA (128 threads) per sorted batch.
// Thread i owns E-row i (exp(trans[i][:])) packed f32x2 in 128 regs, and
// alpha[i] in a register. Per step, shift c = alpha[0]:
//   p[j] = exp(alpha[j]-c);  s_i = E[i]·p;  alpha[i] = c + log(s_i) + x[t,i]
// Two barriers per step. x prefetched one step ahead.
// ---------------------------------------------------------------------------
__global__ __launch_bounds__(128, 2)
void crf_forward_kernel(const float* __restrict__ x,
                        const float* __restrict__ trans)
{
    __shared__ __align__(16) float sh_p[Tsz];
    __shared__ float sh_c;
    __shared__ float sh_red[4];

    const int tid  = threadIdx.x;
    const int lane = tid & 31;
    const int warp = tid >> 5;
    const int b    = g_order[blockIdx.x];
    const int len  = g_slen[blockIdx.x];

    // E row i, packed pairs: e2[2q],e2[2q+1] cover trans[i][4q..4q+3]
    unsigned long long e2[64];
    const float4* trow = reinterpret_cast<const float4*>(trans + tid * Tsz);
    #pragma unroll
    for (int q = 0; q < 32; q++) {
        float4 v4 = trow[q];
        e2[2*q    ] = pack2(__expf(v4.x), __expf(v4.y));
        e2[2*q + 1] = pack2(__expf(v4.z), __expf(v4.w));
    }

    float alpha = (tid == 0) ? 0.0f : NEGV;    // START_ID = 0
    if (tid == 0) sh_c = 0.0f;
    __syncthreads();

    const float* xb = x + (size_t)b * Ssz * Tsz;
    float xr = __ldg(xb + tid);                // x for t = 0

    for (int t = 0; t < len; t++) {
        float c = sh_c;
        sh_p[tid] = __expf(alpha - c);
        // prefetch next step's x (hides DRAM latency behind the matvec)
        float xn = (t + 1 < len) ? __ldg(xb + (size_t)(t + 1) * Tsz + tid) : 0.0f;
        __syncthreads();                       // p visible

        const ulonglong2* p2 = reinterpret_cast<const ulonglong2*>(sh_p);
        unsigned long long a0=0ull,a1=0ull,a2=0ull,a3=0ull,
                           a4=0ull,a5=0ull,a6=0ull,a7=0ull;
        #pragma unroll
        for (int q = 0; q < 32; q += 4) {
            ulonglong2 u0 = p2[q+0];
            ulonglong2 u1 = p2[q+1];
            ulonglong2 u2 = p2[q+2];
            ulonglong2 u3 = p2[q+3];
            ffma2(a0, e2[2*q + 0], u0.x);
            ffma2(a1, e2[2*q + 1], u0.y);
            ffma2(a2, e2[2*q + 2], u1.x);
            ffma2(a3, e2[2*q + 3], u1.y);
            ffma2(a4, e2[2*q + 4], u2.x);
            ffma2(a5, e2[2*q + 5], u2.y);
            ffma2(a6, e2[2*q + 6], u3.x);
            ffma2(a7, e2[2*q + 7], u3.y);
        }
        unsigned long long s01 = addp(addp(a0, a1), addp(a2, a3));
        unsigned long long s23 = addp(addp(a4, a5), addp(a6, a7));
        float s = unpack_sum(addp(s01, s23));

        alpha = c + __logf(s) + xr;
        xr = xn;
        if (tid == 0) sh_c = alpha;
        __syncthreads();                       // c visible; p reads done
    }

    // final: fwd[b] = LSE_i(alpha[i] + trans[END_ID=1][i])
    float v = alpha + __ldg(trans + 1 * Tsz + tid);
    float wm = v;
    #pragma unroll
    for (int off = 16; off > 0; off >>= 1)
        wm = fmaxf(wm, __shfl_xor_sync(0xffffffffu, wm, off));
    if (lane == 0) sh_red[warp] = wm;
    __syncthreads();
    float m = fmaxf(fmaxf(sh_red[0], sh_red[1]), fmaxf(sh_red[2], sh_red[3]));

    float ws = __expf(v - m);
    #pragma unroll
    for (int off = 16; off > 0; off >>= 1)
        ws += __shfl_xor_sync(0xffffffffu, ws, off);
    __syncthreads();
    if (lane == 0) sh_red[warp] = ws;
    __syncthreads();
    if (tid == 0)
        g_fwd[b] = m + __logf(sh_red[0] + sh_red[1] + sh_red[2] + sh_red[3]);
}

// ---------------------------------------------------------------------------
// Kernel 4: gold score.
// ---------------------------------------------------------------------------
__global__ __launch_bounds__(128)
void crf_gold_kernel(const float* __restrict__ x,
                     const int*   __restrict__ tags,
                     const float* __restrict__ mask,
                     const float* __restrict__ trans)
{
    __shared__ float sh_acc[4];
    __shared__ int   sh_len[4];

    const int b    = blockIdx.x;
    const int tid  = threadIdx.x;
    const int warp = tid >> 5;
    const int lane = tid & 31;

    const int*   tg = tags + (size_t)b * Ssz;
    const float* mk = mask + (size_t)b * Ssz;

    float acc = 0.0f;
    int   len = 0;
    for (int t = tid; t < Ssz - 1; t += 128) {
        float mt = mk[t];
        if (mt != 0.0f) {
            int tnext = tg[t + 1];
            int tcur  = tg[t];
            float em  = x[((size_t)b * Ssz + t) * Tsz + tnext];
            float tr  = trans[tnext * Tsz + tcur];
            acc += em + tr;
            len += 1;
        }
    }
    #pragma unroll
    for (int off = 16; off > 0; off >>= 1) {
        acc += __shfl_xor_sync(0xffffffffu, acc, off);
        len += __shfl_xor_sync(0xffffffffu, len, off);
    }
    if (lane == 0) { sh_acc[warp] = acc; sh_len[warp] = len; }
    __syncthreads();
    if (tid == 0) {
        float total = sh_acc[0] + sh_acc[1] + sh_acc[2] + sh_acc[3];
        int   L     = sh_len[0] + sh_len[1] + sh_len[2] + sh_len[3];
        int last_tag = tg[L];
        g_gold[b] = total + trans[1 * Tsz + last_tag];   // END_ID = 1
    }
}

// ---------------------------------------------------------------------------
// Kernel 5: out[0] = mean(fwd - gold)
// ---------------------------------------------------------------------------
__global__ __launch_bounds__(512)
void crf_reduce_kernel(float* __restrict__ out)
{
    __shared__ float sh[16];
    const int tid  = threadIdx.x;
    const int warp = tid >> 5;
    const int lane = tid & 31;

    float d = g_fwd[tid] - g_gold[tid];
    #pragma unroll
    for (int off = 16; off > 0; off >>= 1)
        d += __shfl_xor_sync(0xffffffffu, d, off);
    if (lane == 0) sh[warp] = d;
    __syncthreads();
    if (warp == 0) {
        float v = (lane < 16) ? sh[lane] : 0.0f;
        #pragma unroll
        for (int off = 8; off > 0; off >>= 1)
            v += __shfl_xor_sync(0xffffffffu, v, off);
        if (lane == 0) out[0] = v * (1.0f / (float)Bsz);
    }
}

extern "C" void kernel_launch(void* const* d_in, const int* in_sizes, int n_in,
                              void* d_out, int out_size)
{
    const float* x     = (const float*)d_in[0];
    const int*   tags  = (const int*)  d_in[1];
    const float* mask  = (const float*)d_in[2];
    const float* trans = (const float*)d_in[3];
    float* out = (float*)d_out;

    crf_len_kernel    <<<Bsz, 128>>>(mask);
    crf_sort_kernel   <<<1,   512>>>();
    crf_forward_kernel<<<Bsz, 128>>>(x, trans);
    crf_gold_kernel   <<<Bsz, 128>>>(x, tags, mask, trans);
    crf_reduce_kernel <<<1,   512>>>(out);
}

// round 3
// speedup vs baseline: 2.6892x; 1.1019x over previous
#include <cuda_runtime.h>
#include <cuda_bf16.h>
#include <math.h>

#define Bsz 512
#define Ssz 512
#define Tsz 128
#define NEGV -10000.0f

// scratch (no allocations allowed)
__device__ float g_fwd[Bsz];
__device__ float g_gold[Bsz];
__device__ int   g_len[Bsz];
__device__ int   g_order[Bsz];
__device__ int   g_slen[Bsz];

// ---- packed f32x2 helpers (sm_100+) ----
__device__ __forceinline__ unsigned long long pack2(float lo, float hi) {
    unsigned long long r;
    asm("mov.b64 %0, {%1, %2};" : "=l"(r) : "f"(lo), "f"(hi));
    return r;
}
__device__ __forceinline__ void ffma2(unsigned long long& d,
                                      unsigned long long a,
                                      unsigned long long b) {
    asm("fma.rn.f32x2 %0, %1, %2, %0;" : "+l"(d) : "l"(a), "l"(b));
}
__device__ __forceinline__ unsigned long long addp(unsigned long long a,
                                                   unsigned long long b) {
    unsigned long long r;
    asm("add.rn.f32x2 %0, %1, %2;" : "=l"(r) : "l"(a), "l"(b));
    return r;
}
__device__ __forceinline__ float unpack_sum(unsigned long long a) {
    float lo, hi;
    asm("mov.b64 {%0, %1}, %2;" : "=f"(lo), "=f"(hi) : "l"(a));
    return lo + hi;
}

// ---------------------------------------------------------------------------
// Kernel 1: lengths.  len[b] = sum(mask[b,:])
// ---------------------------------------------------------------------------
__global__ __launch_bounds__(128)
void crf_len_kernel(const float* __restrict__ mask)
{
    __shared__ float sh[4];
    const int b = blockIdx.x, tid = threadIdx.x;
    const int warp = tid >> 5, lane = tid & 31;
    const float4* mb = reinterpret_cast<const float4*>(mask + (size_t)b * Ssz);
    float4 v = mb[tid];
    float s = v.x + v.y + v.z + v.w;
    #pragma unroll
    for (int off = 16; off > 0; off >>= 1)
        s += __shfl_xor_sync(0xffffffffu, s, off);
    if (lane == 0) sh[warp] = s;
    __syncthreads();
    if (tid == 0)
        g_len[b] = (int)(sh[0] + sh[1] + sh[2] + sh[3] + 0.5f);
}

// ---------------------------------------------------------------------------
// Kernel 2: bitonic sort 512 (len,b) keys, descending (longest first).
// ---------------------------------------------------------------------------
__global__ __launch_bounds__(512)
void crf_sort_kernel()
{
    __shared__ int keys[Bsz];
    const int tid = threadIdx.x;
    keys[tid] = (g_len[tid] << 16) | tid;
    __syncthreads();
    for (int k = 2; k <= Bsz; k <<= 1) {
        for (int j = k >> 1; j > 0; j >>= 1) {
            int ixj = tid ^ j;
            if (ixj > tid) {
                int a = keys[tid];
                int b2 = keys[ixj];
                bool up = ((tid & k) == 0);
                if (up ? (a < b2) : (a > b2)) {
                    keys[tid] = b2;
                    keys[ixj] = a;
                }
            }
            __syncthreads();
        }
    }
    g_order[tid] = keys[tid] & 0xFFFF;
    g_slen[tid]  = keys[tid] >> 16;
}

// ---------------------------------------------------------------------------
// Kernel 3: forward scan + gold score. One CTA (128 threads) per sorted batch.
// Thread i owns E-row i (exp(trans[i][:])) packed f32x2, alpha[i] in register.
// Single barrier per step: shift is one step stale (c_known = alpha_0 of the
// previous step, published together with p in the same write phase).
// p double-buffered so one barrier suffices (bar t+1 separates iter-t reads
// from iter-t+2 writes to the same buffer).
// ---------------------------------------------------------------------------
__global__ __launch_bounds__(128, 2)
void crf_forward_kernel(const float* __restrict__ x,
                        const int*   __restrict__ tags,
                        const float* __restrict__ trans)
{
    __shared__ __align__(16) float sh_p[2][Tsz];
    __shared__ float sh_c[2];
    __shared__ float sh_red[4];

    const int tid  = threadIdx.x;
    const int lane = tid & 31;
    const int warp = tid >> 5;
    const int b    = g_order[blockIdx.x];
    const int len  = g_slen[blockIdx.x];

    // E row tid, packed pairs: e2[2q],e2[2q+1] cover trans[tid][4q..4q+3]
    unsigned long long e2[64];
    const float4* trow = reinterpret_cast<const float4*>(trans + tid * Tsz);
    #pragma unroll
    for (int q = 0; q < 32; q++) {
        float4 v4 = trow[q];
        e2[2*q    ] = pack2(__expf(v4.x), __expf(v4.y));
        e2[2*q + 1] = pack2(__expf(v4.z), __expf(v4.w));
    }

    float alpha   = (tid == 0) ? 0.0f : NEGV;    // START_ID = 0
    float c_known = 0.0f;                        // == alpha[0] at t=0 exactly

    const float* xb = x + (size_t)b * Ssz * Tsz;
    float xr = __ldg(xb + tid);                  // x for t = 0

    for (int t = 0; t < len; t++) {
        const int buf = t & 1;
        sh_p[buf][tid] = __expf(alpha - c_known);
        if (tid == 0) sh_c[buf] = alpha;         // next step's shift
        // prefetch next x (clamped; unused on last iter)
        int tn = (t + 1 < len) ? (t + 1) : t;
        float xn = __ldg(xb + (size_t)tn * Tsz + tid);
        __syncthreads();                         // ONE barrier per step

        float c_next = sh_c[buf];
        const ulonglong2* p2 = reinterpret_cast<const ulonglong2*>(sh_p[buf]);
        unsigned long long a0=0ull,a1=0ull,a2=0ull,a3=0ull,
                           a4=0ull,a5=0ull,a6=0ull,a7=0ull;
        #pragma unroll
        for (int q = 0; q < 32; q += 4) {
            ulonglong2 u0 = p2[q+0];
            ulonglong2 u1 = p2[q+1];
            ulonglong2 u2 = p2[q+2];
            ulonglong2 u3 = p2[q+3];
            ffma2(a0, e2[2*q + 0], u0.x);
            ffma2(a1, e2[2*q + 1], u0.y);
            ffma2(a2, e2[2*q + 2], u1.x);
            ffma2(a3, e2[2*q + 3], u1.y);
            ffma2(a4, e2[2*q + 4], u2.x);
            ffma2(a5, e2[2*q + 5], u2.y);
            ffma2(a6, e2[2*q + 6], u3.x);
            ffma2(a7, e2[2*q + 7], u3.y);
        }
        unsigned long long s01 = addp(addp(a0, a1), addp(a2, a3));
        unsigned long long s23 = addp(addp(a4, a5), addp(a6, a7));
        float s = unpack_sum(addp(s01, s23));

        alpha   = c_known + __logf(s) + xr;      // exact for any shift
        xr      = xn;
        c_known = c_next;                        // one step stale, bounded drift
    }

    // ---- final: fwd[b] = LSE_i(alpha[i] + trans[END_ID=1][i]) ----
    float v = alpha + __ldg(trans + 1 * Tsz + tid);
    float wm = v;
    #pragma unroll
    for (int off = 16; off > 0; off >>= 1)
        wm = fmaxf(wm, __shfl_xor_sync(0xffffffffu, wm, off));
    if (lane == 0) sh_red[warp] = wm;
    __syncthreads();
    float m = fmaxf(fmaxf(sh_red[0], sh_red[1]), fmaxf(sh_red[2], sh_red[3]));

    float ws = __expf(v - m);
    #pragma unroll
    for (int off = 16; off > 0; off >>= 1)
        ws += __shfl_xor_sync(0xffffffffu, ws, off);
    __syncthreads();
    if (lane == 0) sh_red[warp] = ws;
    __syncthreads();
    if (tid == 0)
        g_fwd[b] = m + __logf(sh_red[0] + sh_red[1] + sh_red[2] + sh_red[3]);

    // ---- gold score for the same batch (mask==1 <=> t < len) ----
    const int* tg = tags + (size_t)b * Ssz;
    float acc = 0.0f;
    for (int t2 = tid; t2 < len; t2 += 128) {
        int tnext = tg[t2 + 1];
        int tcur  = tg[t2];
        acc += xb[(size_t)t2 * Tsz + tnext] + __ldg(trans + tnext * Tsz + tcur);
    }
    #pragma unroll
    for (int off = 16; off > 0; off >>= 1)
        acc += __shfl_xor_sync(0xffffffffu, acc, off);
    __syncthreads();                              // sh_red reuse safe
    if (lane == 0) sh_red[warp] = acc;
    __syncthreads();
    if (tid == 0) {
        float total = sh_red[0] + sh_red[1] + sh_red[2] + sh_red[3];
        g_gold[b] = total + __ldg(trans + 1 * Tsz + tg[len]);   // END_ID = 1
    }
}

// ---------------------------------------------------------------------------
// Kernel 4: out[0] = mean(fwd - gold)
// ---------------------------------------------------------------------------
__global__ __launch_bounds__(512)
void crf_reduce_kernel(float* __restrict__ out)
{
    __shared__ float sh[16];
    const int tid  = threadIdx.x;
    const int warp = tid >> 5;
    const int lane = tid & 31;

    float d = g_fwd[tid] - g_gold[tid];
    #pragma unroll
    for (int off = 16; off > 0; off >>= 1)
        d += __shfl_xor_sync(0xffffffffu, d, off);
    if (lane == 0) sh[warp] = d;
    __syncthreads();
    if (warp == 0) {
        float v = (lane < 16) ? sh[lane] : 0.0f;
        #pragma unroll
        for (int off = 8; off > 0; off >>= 1)
            v += __shfl_xor_sync(0xffffffffu, v, off);
        if (lane == 0) out[0] = v * (1.0f / (float)Bsz);
    }
}

extern "C" void kernel_launch(void* const* d_in, const int* in_sizes, int n_in,
                              void* d_out, int out_size)
{
    const float* x     = (const float*)d_in[0];
    const int*   tags  = (const int*)  d_in[1];
    const float* mask  = (const float*)d_in[2];
    const float* trans = (const float*)d_in[3];
    float* out = (float*)d_out;

    crf_len_kernel    <<<Bsz, 128>>>(mask);
    crf_sort_kernel   <<<1,   512>>>();
    crf_forward_kernel<<<Bsz, 128>>>(x, tags, trans);
    crf_reduce_kernel <<<1,   512>>>(out);
}